// round 2
// baseline (speedup 1.0000x reference)
#include <cuda_runtime.h>
#include <cuda_bf16.h>

// Problem constants
#define NF 8
#define V 12
#define D 64
#define BATCH 131072
#define NPAIR 28            // C(8,2)
#define GRAM_ELEMS (NPAIR * V * V)   // 4032 floats = 16128 B

// Precomputed tables (device globals: no allocation allowed)
__device__ float  g_gram[GRAM_ELEMS];     // [pair][i][j] = dot(emb[f][i], emb[g][j]), pairs in (f<g) nested order
__device__ float4 g_pf[NF * V];           // (.x = dot(e, a0), .y = dot(e, a1), .z = first_order, .w = 0)
__device__ double g_loss_acc;

// ---------------------------------------------------------------------------
// Kernel 1: precompute gram + per-(field,vocab) fused tables, zero loss acc.
// Blocks 0..27: gram pair p. Block 28: PF table + zero accumulator.
// ---------------------------------------------------------------------------
__global__ void precompute_kernel(const float* __restrict__ emb,
                                  const float* __restrict__ emb_first,
                                  const float* __restrict__ a_emb)
{
    int p = blockIdx.x;
    int t = threadIdx.x;

    if (p < NPAIR) {
        // Decode pair p -> (f, g), f < g, enumeration order (0,1),(0,2),...,(6,7)
        int f = 0, g = 1;
        {
            int c = p;
            for (int ff = 0; ff < NF; ++ff) {
                int cnt = NF - 1 - ff;
                if (c < cnt) { f = ff; g = ff + 1 + c; break; }
                c -= cnt;
            }
        }
        if (t < V * V) {
            int i = t / V, j = t % V;
            const float4* ra = (const float4*)(emb + (size_t)(f * V + i) * D);
            const float4* rb = (const float4*)(emb + (size_t)(g * V + j) * D);
            float s = 0.f;
            #pragma unroll
            for (int q = 0; q < D / 4; ++q) {
                float4 a = __ldg(&ra[q]);
                float4 b = __ldg(&rb[q]);
                s += a.x * b.x + a.y * b.y + a.z * b.z + a.w * b.w;
            }
            g_gram[p * (V * V) + i * V + j] = s;
        }
    } else {
        // PF table
        if (t < NF * V) {
            const float4* r  = (const float4*)(emb + (size_t)t * D);
            const float4* a0 = (const float4*)(a_emb);
            const float4* a1 = (const float4*)(a_emb + D);
            float s0 = 0.f, s1 = 0.f;
            #pragma unroll
            for (int q = 0; q < D / 4; ++q) {
                float4 e = __ldg(&r[q]);
                float4 x = __ldg(&a0[q]);
                float4 y = __ldg(&a1[q]);
                s0 += e.x * x.x + e.y * x.y + e.z * x.z + e.w * x.w;
                s1 += e.x * y.x + e.y * y.y + e.z * y.z + e.w * y.w;
            }
            g_pf[t] = make_float4(s0, s1, __ldg(&emb_first[t]), 0.f);
        }
        if (t == 0) g_loss_acc = 0.0;
    }
}

// ---------------------------------------------------------------------------
// Kernel 2: main per-element kernel.
//   inf_k = sum_f P[f][idx_f][k] + sum_f F[f][idx_f] + action_first[k]
//   pair  = sum_{f<g} G[f,g][idx_f][idx_g]
//   loss partial -> block reduce -> double atomicAdd
// ---------------------------------------------------------------------------
#define THREADS 512
#define EPT 2                          // elements per thread
#define BLOCKS (BATCH / (THREADS * EPT))   // 128

__global__ void __launch_bounds__(THREADS)
fm_main_kernel(const int* __restrict__ feats,
               const float* __restrict__ label,
               const float* __restrict__ pos_weights,
               const float* __restrict__ action_first,
               float* __restrict__ out)
{
    __shared__ float  s_gram[GRAM_ELEMS];
    __shared__ float4 s_pf[NF * V];
    __shared__ float  s_wsum[THREADS / 32];

    int tid = threadIdx.x;

    // Stage tables into smem (vectorized: 4032 floats = 1008 float4)
    {
        const float4* src = (const float4*)g_gram;
        float4* dst = (float4*)s_gram;
        for (int k = tid; k < GRAM_ELEMS / 4; k += THREADS) dst[k] = src[k];
        if (tid < NF * V) s_pf[tid] = g_pf[tid];
    }
    __syncthreads();

    const float af0 = __ldg(&action_first[0]);
    const float af1 = __ldg(&action_first[1]);

    float lsum = 0.f;

    #pragma unroll
    for (int e = 0; e < EPT; ++e) {
        int b = blockIdx.x * (THREADS * EPT) + e * THREADS + tid;

        // Gather field indices (coalesced across warp: feats is [field][batch])
        int idx12[NF];  // idx * 12, and idx itself
        int idx[NF];
        #pragma unroll
        for (int f = 0; f < NF; ++f) {
            int v = __ldg(&feats[f * BATCH + b]);
            idx[f] = v;
            idx12[f] = v * V;
        }

        // First order + action dots
        float d0 = 0.f, d1 = 0.f, fo = 0.f;
        #pragma unroll
        for (int f = 0; f < NF; ++f) {
            float4 pf = s_pf[f * V + idx[f]];
            d0 += pf.x; d1 += pf.y; fo += pf.z;
        }

        // Pairwise term
        float pair = 0.f;
        int p = 0;
        #pragma unroll
        for (int f = 0; f < NF; ++f) {
            #pragma unroll
            for (int g = f + 1; g < NF; ++g) {
                pair += s_gram[p * (V * V) + idx12[f] + idx[g]];
                ++p;
            }
        }

        float inf0 = d0 + fo + af0;
        float inf1 = d1 + fo + af1;

        float2 lab = __ldg(((const float2*)label) + b);
        float2 pw  = __ldg(((const float2*)pos_weights) + b);
        float e0 = inf0 - lab.x;
        float e1 = inf1 - lab.y;
        lsum += pw.x * e0 * e0 + pw.y * e1 * e1;

        // Outputs: inferences [B,2] at [0, 2B), loss scalar at 2B, pair [B,1] at (2B, 2B+1+B)
        ((float2*)out)[b] = make_float2(inf0, inf1);
        out[2 * BATCH + 1 + b] = pair;
    }

    // Block reduction of weighted loss
    #pragma unroll
    for (int o = 16; o > 0; o >>= 1) lsum += __shfl_xor_sync(0xffffffffu, lsum, o);
    if ((tid & 31) == 0) s_wsum[tid >> 5] = lsum;
    __syncthreads();
    if (tid < (THREADS / 32)) {
        float v = s_wsum[tid];
        #pragma unroll
        for (int o = (THREADS / 64); o > 0; o >>= 1)
            v += __shfl_xor_sync(0xffffffffu, v, o);
        if (tid == 0) atomicAdd(&g_loss_acc, (double)v);
    }
}

// ---------------------------------------------------------------------------
// Kernel 3: finalize loss (mean over batch)
// ---------------------------------------------------------------------------
__global__ void finalize_kernel(float* __restrict__ out)
{
    out[2 * BATCH] = (float)(g_loss_acc * (1.0 / (double)BATCH));
}

// ---------------------------------------------------------------------------
// Launch: inputs per metadata order:
//   0 emb_tables (8,12,64) f32
//   1 emb_first  (8,12,1)  f32
//   2 action_emb (2,64)    f32
//   3 action_first (2,1)   f32
//   4 label      (B,2)     f32
//   5 pos_weights(B,2)     f32
//   6 feats      (8,B)     i32
// Output: [inferences (B,2) | loss (1) | pair (B,1)] flattened f32
// ---------------------------------------------------------------------------
extern "C" void kernel_launch(void* const* d_in, const int* in_sizes, int n_in,
                              void* d_out, int out_size)
{
    const float* emb_tables   = (const float*)d_in[0];
    const float* emb_first    = (const float*)d_in[1];
    const float* action_emb   = (const float*)d_in[2];
    const float* action_first = (const float*)d_in[3];
    const float* label        = (const float*)d_in[4];
    const float* pos_weights  = (const float*)d_in[5];
    const int*   feats        = (const int*)d_in[6];
    float* out = (float*)d_out;

    precompute_kernel<<<NPAIR + 1, 192>>>(emb_tables, emb_first, action_emb);
    fm_main_kernel<<<BLOCKS, THREADS>>>(feats, label, pos_weights, action_first, out);
    finalize_kernel<<<1, 1>>>(out);
}

// round 7
// speedup vs baseline: 1.0277x; 1.0277x over previous
#include <cuda_runtime.h>
#include <cuda_bf16.h>

// Problem constants
#define NF 8
#define V 12
#define D 64
#define BATCH 131072
#define NPAIR 28                       // C(8,2)
#define GRAM_ELEMS (NPAIR * V * V)     // 4032 floats = 16128 B

// Precomputed tables + reduction scratch (device globals: no allocation allowed)
__device__ float  g_gram[GRAM_ELEMS];   // [pair][i][j] = dot(emb[f][i], emb[g][j])
__device__ float4 g_pf[NF * V];         // (.x=dot(e,a0), .y=dot(e,a1), .z=first_order, .w=0)
__device__ float  g_partial[256];       // per-block weighted-loss partials

__device__ __forceinline__ float dot4(float4 a, float4 b) {
    return a.x * b.x + a.y * b.y + a.z * b.z + a.w * b.w;
}

// ---------------------------------------------------------------------------
// Kernel 1: precompute gram + PF tables.
// Each 64-length dot split across 4 threads (16 floats each), shfl-reduced.
// 4032 gram dots + 96 PF units = 4128 units * 4 threads = 16512 (516 warps,
// warp-aligned so early-exit never splits a warp).
// ---------------------------------------------------------------------------
#define PRE_THREADS 256
#define GRAM_DOTS 4032
#define TOTAL_DOTS (GRAM_DOTS + NF * V)                                // 4128
#define PRE_BLOCKS ((TOTAL_DOTS * 4 + PRE_THREADS - 1) / PRE_THREADS)  // 65

__global__ void __launch_bounds__(PRE_THREADS)
precompute_kernel(const float* __restrict__ emb,
                  const float* __restrict__ emb_first,
                  const float* __restrict__ a_emb)
{
    int gid  = blockIdx.x * PRE_THREADS + threadIdx.x;
    int dot  = gid >> 2;
    int part = gid & 3;                 // which 16-float chunk of the 64-dot
    if (dot >= TOTAL_DOTS) return;      // whole warps only (16512 % 32 == 0)

    if (dot < GRAM_DOTS) {
        int p = dot / (V * V);
        int r = dot - p * (V * V);
        int i = r / V, j = r - (r / V) * V;
        // decode pair p -> (f, g), f < g, order (0,1),(0,2),...,(6,7)
        int f = 0, g = 1, c = p;
        #pragma unroll
        for (int ff = 0; ff < NF - 1; ++ff) {
            int cnt = NF - 1 - ff;
            if (c < cnt) { f = ff; g = ff + 1 + c; break; }
            c -= cnt;
        }
        const float4* ra = (const float4*)(emb + (size_t)(f * V + i) * D) + part * 4;
        const float4* rb = (const float4*)(emb + (size_t)(g * V + j) * D) + part * 4;
        float4 a0 = __ldg(&ra[0]), b0 = __ldg(&rb[0]);
        float4 a1 = __ldg(&ra[1]), b1 = __ldg(&rb[1]);
        float4 a2 = __ldg(&ra[2]), b2 = __ldg(&rb[2]);
        float4 a3 = __ldg(&ra[3]), b3 = __ldg(&rb[3]);
        float s  = (dot4(a0, b0) + dot4(a2, b2)) + (dot4(a1, b1) + dot4(a3, b3));
        s += __shfl_xor_sync(0xffffffffu, s, 1);
        s += __shfl_xor_sync(0xffffffffu, s, 2);
        if (part == 0) g_gram[dot] = s;
    } else {
        int t = dot - GRAM_DOTS;        // 0..95 = f*V + i
        const float4* rr = (const float4*)(emb + (size_t)t * D) + part * 4;
        const float4* a0 = (const float4*)(a_emb) + part * 4;
        const float4* a1 = (const float4*)(a_emb + D) + part * 4;
        float s0 = 0.f, s1 = 0.f;
        #pragma unroll
        for (int q = 0; q < 4; ++q) {
            float4 e = __ldg(&rr[q]);
            float4 x = __ldg(&a0[q]);
            float4 y = __ldg(&a1[q]);
            s0 += dot4(e, x);
            s1 += dot4(e, y);
        }
        s0 += __shfl_xor_sync(0xffffffffu, s0, 1);
        s0 += __shfl_xor_sync(0xffffffffu, s0, 2);
        s1 += __shfl_xor_sync(0xffffffffu, s1, 1);
        s1 += __shfl_xor_sync(0xffffffffu, s1, 2);
        if (part == 0) g_pf[t] = make_float4(s0, s1, __ldg(&emb_first[t]), 0.f);
    }
}

// ---------------------------------------------------------------------------
// Kernel 2: main per-element kernel. Writes per-block loss partials; no atomics.
// All warp shuffles are full-warp (32 active lanes) -> no partial-mask UB.
// ---------------------------------------------------------------------------
#define THREADS 512
#define NBLK 256                       // 256 * 512 = 131072 = BATCH

__global__ void __launch_bounds__(THREADS)
fm_main_kernel(const int* __restrict__ feats,
               const float* __restrict__ label,
               const float* __restrict__ pos_weights,
               const float* __restrict__ action_first,
               float* __restrict__ out)
{
    __shared__ float  s_gram[GRAM_ELEMS];
    __shared__ float4 s_pf[NF * V];
    __shared__ float  s_wsum[THREADS / 32];

    int tid = threadIdx.x;

    // Stage tables into smem (vectorized)
    {
        const float4* src = (const float4*)g_gram;
        float4* dst = (float4*)s_gram;
        for (int k = tid; k < GRAM_ELEMS / 4; k += THREADS) dst[k] = src[k];
        if (tid < NF * V) s_pf[tid] = g_pf[tid];
    }
    __syncthreads();

    const float af0 = __ldg(&action_first[0]);
    const float af1 = __ldg(&action_first[1]);

    int b = blockIdx.x * THREADS + tid;

    // Gather field indices (coalesced: feats is [field][batch])
    int idx[NF], idx12[NF];
    #pragma unroll
    for (int f = 0; f < NF; ++f) {
        int v = __ldg(&feats[f * BATCH + b]);
        idx[f]   = v;
        idx12[f] = v * V;
    }

    // First order + action dots (8 LDS.128)
    float d0 = 0.f, d1 = 0.f, fo = 0.f;
    #pragma unroll
    for (int f = 0; f < NF; ++f) {
        float4 pf = s_pf[f * V + idx[f]];
        d0 += pf.x; d1 += pf.y; fo += pf.z;
    }

    // Pairwise term: 28 gathered LDS.32
    float pair = 0.f;
    int p = 0;
    #pragma unroll
    for (int f = 0; f < NF; ++f) {
        #pragma unroll
        for (int g = f + 1; g < NF; ++g) {
            pair += s_gram[p * (V * V) + idx12[f] + idx[g]];
            ++p;
        }
    }

    float inf0 = d0 + fo + af0;
    float inf1 = d1 + fo + af1;

    float2 lab = __ldg(((const float2*)label) + b);
    float2 pw  = __ldg(((const float2*)pos_weights) + b);
    float e0 = inf0 - lab.x;
    float e1 = inf1 - lab.y;
    float lsum = pw.x * e0 * e0 + pw.y * e1 * e1;

    // Outputs: inferences [B,2] at [0,2B), loss at 2B, pair [B,1] at (2B,2B+1+B)
    ((float2*)out)[b] = make_float2(inf0, inf1);
    out[2 * BATCH + 1 + b] = pair;

    // Block reduction of weighted loss (full-warp shuffles only)
    #pragma unroll
    for (int o = 16; o > 0; o >>= 1) lsum += __shfl_xor_sync(0xffffffffu, lsum, o);
    if ((tid & 31) == 0) s_wsum[tid >> 5] = lsum;
    __syncthreads();
    if (tid < 32) {                              // full warp active
        float v = (tid < THREADS / 32) ? s_wsum[tid] : 0.f;
        #pragma unroll
        for (int o = 16; o > 0; o >>= 1) v += __shfl_xor_sync(0xffffffffu, v, o);
        if (tid == 0) g_partial[blockIdx.x] = v;
    }
}

// ---------------------------------------------------------------------------
// Kernel 3: finalize loss (deterministic tree reduce of 256 partials).
// ---------------------------------------------------------------------------
__global__ void __launch_bounds__(256)
finalize_kernel(float* __restrict__ out)
{
    __shared__ float s_w[8];
    int tid = threadIdx.x;
    float v = g_partial[tid];
    #pragma unroll
    for (int o = 16; o > 0; o >>= 1) v += __shfl_xor_sync(0xffffffffu, v, o);
    if ((tid & 31) == 0) s_w[tid >> 5] = v;
    __syncthreads();
    if (tid < 32) {                              // full warp active
        float w = (tid < 8) ? s_w[tid] : 0.f;
        #pragma unroll
        for (int o = 16; o > 0; o >>= 1) w += __shfl_xor_sync(0xffffffffu, w, o);
        if (tid == 0) out[2 * BATCH] = w * (1.0f / (float)BATCH);
    }
}

// ---------------------------------------------------------------------------
// Launch. Inputs (metadata order):
//   0 emb_tables (8,12,64) f32   1 emb_first (8,12,1) f32
//   2 action_emb (2,64) f32      3 action_first (2,1) f32
//   4 label (B,2) f32            5 pos_weights (B,2) f32
//   6 feats (8,B) i32
// Output: [inferences (B,2) | loss (1) | pair (B,1)] f32
// ---------------------------------------------------------------------------
extern "C" void kernel_launch(void* const* d_in, const int* in_sizes, int n_in,
                              void* d_out, int out_size)
{
    const float* emb_tables   = (const float*)d_in[0];
    const float* emb_first    = (const float*)d_in[1];
    const float* action_emb   = (const float*)d_in[2];
    const float* action_first = (const float*)d_in[3];
    const float* label        = (const float*)d_in[4];
    const float* pos_weights  = (const float*)d_in[5];
    const int*   feats        = (const int*)d_in[6];
    float* out = (float*)d_out;

    precompute_kernel<<<PRE_BLOCKS, PRE_THREADS>>>(emb_tables, emb_first, action_emb);
    fm_main_kernel<<<NBLK, THREADS>>>(feats, label, pos_weights, action_first, out);
    finalize_kernel<<<1, 256>>>(out);
}